// round 3
// baseline (speedup 1.0000x reference)
#include <cuda_runtime.h>
#include <cstdint>
#include <cstddef>

#define MAXN 10000
#define MAXE 160000

__device__ float g_x0[MAXN * 16];
__device__ float g_x1[MAXN * 12];
__device__ float g_qd0[MAXN * 8];
__device__ float g_qd1[MAXN * 6];
__device__ float g_logit[MAXE];
__device__ float g_v[MAXE * 28];     // SoA: [j*E + e]
__device__ float g_m[MAXN];
__device__ float g_z[MAXN];
__device__ float g_agg[MAXN * 28];   // AoS

__device__ __forceinline__ float frelu(float x) { return x > 0.f ? x : 0.f; }

template <int NF4>
__device__ __forceinline__ float dotf4(const float4* __restrict__ w,
                                       const float* __restrict__ h) {
    float s0 = 0.f, s1 = 0.f, s2 = 0.f, s3 = 0.f;
#pragma unroll
    for (int t = 0; t < NF4; t++) {
        float4 ww = w[t];
        s0 = fmaf(h[4 * t + 0], ww.x, s0);
        s1 = fmaf(h[4 * t + 1], ww.y, s1);
        s2 = fmaf(h[4 * t + 2], ww.z, s2);
        s3 = fmaf(h[4 * t + 3], ww.w, s3);
    }
    return (s0 + s1) + (s2 + s3);
}

__device__ __forceinline__ void atomicMaxF(float* addr, float v) {
    if (v >= 0.f) atomicMax((int*)addr, __float_as_int(v));
    else          atomicMin((unsigned int*)addr, __float_as_uint(v));
}

// ---------------------------------------------------------------------------
// Kernel A: node prep (x = ir_linear(node_attr); qd = (q @ Wd) precontracted)
// ---------------------------------------------------------------------------
__global__ void node_prep_kernel(const float* __restrict__ na,
                                 const float* __restrict__ Win0,
                                 const float* __restrict__ Win1,
                                 const float* __restrict__ Wq0,
                                 const float* __restrict__ Wq1,
                                 const float* __restrict__ Wd0,
                                 const float* __restrict__ Wd1,
                                 int N) {
    __shared__ float sWin0[512], sWin1[32], sWq0[128], sWq1[8], sWd0[64], sWd1[4];
    int tid = threadIdx.x;
    for (int i = tid; i < 512; i += blockDim.x) sWin0[i] = Win0[i];
    for (int i = tid; i < 32;  i += blockDim.x) sWin1[i] = Win1[i];
    for (int i = tid; i < 128; i += blockDim.x) sWq0[i]  = Wq0[i];
    for (int i = tid; i < 8;   i += blockDim.x) sWq1[i]  = Wq1[i];
    for (int i = tid; i < 64;  i += blockDim.x) sWd0[i]  = Wd0[i];
    for (int i = tid; i < 4;   i += blockDim.x) sWd1[i]  = Wd1[i];
    __syncthreads();

    int n = blockIdx.x * blockDim.x + tid;
    if (n >= N) return;

    const float* p = na + (size_t)n * 56;
    float a0[32], a1[24];
#pragma unroll
    for (int i = 0; i < 32; i++) a0[i] = p[i];
#pragma unroll
    for (int i = 0; i < 24; i++) a1[i] = p[32 + i];

    float x0[16];
#pragma unroll
    for (int o = 0; o < 16; o++) {
        float s = 0.f;
#pragma unroll
        for (int i = 0; i < 32; i++) s = fmaf(a0[i], sWin0[i * 16 + o], s);
        x0[o] = s * 0.17677669529663687f;   // 1/sqrt(32)
    }
    float x1[12];
#pragma unroll
    for (int o = 0; o < 4; o++)
#pragma unroll
        for (int c = 0; c < 3; c++) {
            float s = 0.f;
#pragma unroll
            for (int m = 0; m < 8; m++) s = fmaf(a1[m * 3 + c], sWin1[m * 4 + o], s);
            x1[o * 3 + c] = s * 0.35355339059327373f;  // 1/sqrt(8)
        }

    float q0[8];
#pragma unroll
    for (int b = 0; b < 8; b++) {
        float s = 0.f;
#pragma unroll
        for (int o = 0; o < 16; o++) s = fmaf(x0[o], sWq0[o * 8 + b], s);
        q0[b] = s * 0.25f;                   // 1/sqrt(16)
    }
    float q1[6];
#pragma unroll
    for (int j = 0; j < 2; j++)
#pragma unroll
        for (int c = 0; c < 3; c++) {
            float s = 0.f;
#pragma unroll
            for (int o = 0; o < 4; o++) s = fmaf(x1[o * 3 + c], sWq1[o * 2 + j], s);
            q1[j * 3 + c] = s * 0.5f;        // 1/sqrt(4)
        }

#pragma unroll
    for (int j = 0; j < 8; j++) {
        float s = 0.f;
#pragma unroll
        for (int i = 0; i < 8; i++) s = fmaf(q0[i], sWd0[i * 8 + j], s);
        g_qd0[(size_t)n * 8 + j] = s;
    }
#pragma unroll
    for (int j = 0; j < 2; j++)
#pragma unroll
        for (int c = 0; c < 3; c++) {
            float s = 0.f;
#pragma unroll
            for (int i = 0; i < 2; i++) s = fmaf(q1[i * 3 + c], sWd1[i * 2 + j], s);
            g_qd1[(size_t)n * 6 + j * 3 + c] = s;
        }

#pragma unroll
    for (int o = 0; o < 16; o++) g_x0[(size_t)n * 16 + o] = x0[o];
#pragma unroll
    for (int o = 0; o < 12; o++) g_x1[(size_t)n * 12 + o] = x1[o];
}

// ---------------------------------------------------------------------------
__global__ void init_kernel(int N) {
    int i = blockIdx.x * blockDim.x + threadIdx.x;
    if (i < N * 28) g_agg[i] = 0.f;
    if (i < N) {
        g_m[i] = __int_as_float(0xff800000);  // -inf
        g_z[i] = 0.f;
    }
}

// ---------------------------------------------------------------------------
// Kernel B: fused edge kernel
// smem layout (floats): K-MLP W1^T,b1,W2^T,b2,W3^T,b3 then V-MLP same.
// ---------------------------------------------------------------------------
#define OW1K 0
#define OB1K 2048
#define OW2K 2112
#define OB2K 6208
#define OW3K 6272
#define OB3K 19072
#define OW1V 19272
#define OB1V 21320
#define OW2V 21384
#define OB2V 25480
#define OW3V 25544
#define OB3V 51144
#define SM_FLOATS 51544

__device__ __forceinline__ void mlp_front(const float* __restrict__ sm,
                                          int oW1, int oB1, int oW2, int oB2,
                                          const float* __restrict__ gEa,
                                          float* __restrict__ h2) {
    float ea[32];
#pragma unroll
    for (int t = 0; t < 8; t++) {
        float4 v = reinterpret_cast<const float4*>(gEa)[t];
        ea[4 * t + 0] = v.x; ea[4 * t + 1] = v.y;
        ea[4 * t + 2] = v.z; ea[4 * t + 3] = v.w;
    }
    float h1[64];
#pragma unroll
    for (int o = 0; o < 64; o++)
        h1[o] = frelu(sm[oB1 + o] +
                      dotf4<8>(reinterpret_cast<const float4*>(sm + oW1 + o * 32), ea));
#pragma unroll
    for (int o = 0; o < 64; o++)
        h2[o] = frelu(sm[oB2 + o] +
                      dotf4<16>(reinterpret_cast<const float4*>(sm + oW2 + o * 64), h1));
}

__global__ void __launch_bounds__(256, 1)
edge_kernel(const float* __restrict__ edge_attr,
            const float* __restrict__ edge_sh,
            const int*   __restrict__ eidx,
            const float* __restrict__ fcW1, const float* __restrict__ fcb1,
            const float* __restrict__ fcW2, const float* __restrict__ fcb2,
            const float* __restrict__ fcW3, const float* __restrict__ fcb3,
            const float* __restrict__ fkW1, const float* __restrict__ fkb1,
            const float* __restrict__ fkW2, const float* __restrict__ fkb2,
            const float* __restrict__ fkW3, const float* __restrict__ fkb3,
            int E) {
    extern __shared__ float sm[];
    int tid = threadIdx.x, bs = blockDim.x;
    for (int i = tid; i < 2048;  i += bs) { int o = i >> 5, c = i & 31; sm[OW1K + i] = fkW1[c * 64 + o]; }
    for (int i = tid; i < 64;    i += bs) sm[OB1K + i] = fkb1[i];
    for (int i = tid; i < 4096;  i += bs) { int o = i >> 6, c = i & 63; sm[OW2K + i] = fkW2[c * 64 + o]; }
    for (int i = tid; i < 64;    i += bs) sm[OB2K + i] = fkb2[i];
    for (int i = tid; i < 12800; i += bs) { int w = i >> 6, c = i & 63; sm[OW3K + i] = fkW3[c * 200 + w]; }
    for (int i = tid; i < 200;   i += bs) sm[OB3K + i] = fkb3[i];
    for (int i = tid; i < 2048;  i += bs) { int o = i >> 5, c = i & 31; sm[OW1V + i] = fcW1[c * 64 + o]; }
    for (int i = tid; i < 64;    i += bs) sm[OB1V + i] = fcb1[i];
    for (int i = tid; i < 4096;  i += bs) { int o = i >> 6, c = i & 63; sm[OW2V + i] = fcW2[c * 64 + o]; }
    for (int i = tid; i < 64;    i += bs) sm[OB2V + i] = fcb2[i];
    for (int i = tid; i < 25600; i += bs) { int w = i >> 6, c = i & 63; sm[OW3V + i] = fcW3[c * 400 + w]; }
    for (int i = tid; i < 400;   i += bs) sm[OB3V + i] = fcb3[i];
    __syncthreads();

    int e = blockIdx.x * bs + tid;
    if (e >= E) return;

    int s = eidx[e];
    int d = eidx[E + e];
    float4 shv = reinterpret_cast<const float4*>(edge_sh)[e];
    float sh0 = shv.x, shx = shv.y, shy = shv.z, shz = shv.w;

    float xl0[16], xl1[12], ul1[4];
#pragma unroll
    for (int o = 0; o < 16; o++) xl0[o] = g_x0[(size_t)s * 16 + o];
#pragma unroll
    for (int o = 0; o < 12; o++) xl1[o] = g_x1[(size_t)s * 12 + o];
#pragma unroll
    for (int j = 0; j < 4; j++)
        ul1[j] = xl1[j * 3] * shx + xl1[j * 3 + 1] * shy + xl1[j * 3 + 2] * shz;

    const float NORM = 0.22360679774997896f;  // 1/sqrt(20)
    const float I3   = 0.5773502691896258f;   // 1/sqrt(3)
    float h2[64];

    // ===================== K path =====================
    mlp_front(sm, OW1K, OB1K, OW2K, OB2K, edge_attr + (size_t)e * 32, h2);
    {
        const float* W3 = sm + OW3K;
        const float* B3 = sm + OB3K;
        float logit = 0.f;
#pragma unroll 1
        for (int b = 0; b < 8; b++) {
            float acc0 = 0.f;
#pragma unroll 1
            for (int a = 0; a < 16; a++) {
                int wi = a * 8 + b;
                float w = dotf4<16>(reinterpret_cast<const float4*>(W3 + wi * 64), h2) + B3[wi];
                acc0 = fmaf(xl0[a], w, acc0);
            }
            float acc1 = 0.f;
#pragma unroll 1
            for (int a = 0; a < 4; a++) {
                int wi = 168 + a * 8 + b;
                float w = dotf4<16>(reinterpret_cast<const float4*>(W3 + wi * 64), h2) + B3[wi];
                acc1 = fmaf(ul1[a], w, acc1);
            }
            float k0b = NORM * fmaf(sh0, acc0, I3 * acc1);
            logit = fmaf(g_qd0[(size_t)d * 8 + b], k0b, logit);
        }
#pragma unroll 1
        for (int j = 0; j < 2; j++) {
            float c01 = 0.f;
#pragma unroll 1
            for (int a = 0; a < 16; a++) {
                int wi = 128 + a * 2 + j;
                float w = dotf4<16>(reinterpret_cast<const float4*>(W3 + wi * 64), h2) + B3[wi];
                c01 = fmaf(xl0[a], w, c01);
            }
            float dx = 0.f, dy = 0.f, dz = 0.f;
#pragma unroll 1
            for (int a = 0; a < 4; a++) {
                int wi = 160 + a * 2 + j;
                float w = dotf4<16>(reinterpret_cast<const float4*>(W3 + wi * 64), h2) + B3[wi];
                dx = fmaf(xl1[a * 3 + 0], w, dx);
                dy = fmaf(xl1[a * 3 + 1], w, dy);
                dz = fmaf(xl1[a * 3 + 2], w, dz);
            }
            float k1x = NORM * (shx * c01 + sh0 * dx);
            float k1y = NORM * (shy * c01 + sh0 * dy);
            float k1z = NORM * (shz * c01 + sh0 * dz);
            logit += I3 * (g_qd1[(size_t)d * 6 + j * 3 + 0] * k1x +
                           g_qd1[(size_t)d * 6 + j * 3 + 1] * k1y +
                           g_qd1[(size_t)d * 6 + j * 3 + 2] * k1z);
        }
        logit *= 0.31622776601683794f;  // 1/sqrt(10)
        g_logit[e] = logit;
        atomicMaxF(&g_m[d], logit);
    }

    // ===================== V path =====================
    mlp_front(sm, OW1V, OB1V, OW2V, OB2V, edge_attr + (size_t)e * 32, h2);
    {
        const float* W3 = sm + OW3V;
        const float* B3 = sm + OB3V;
#pragma unroll 1
        for (int b = 0; b < 16; b++) {
            float acc0 = 0.f;
#pragma unroll 1
            for (int a = 0; a < 16; a++) {
                int wi = a * 16 + b;
                float w = dotf4<16>(reinterpret_cast<const float4*>(W3 + wi * 64), h2) + B3[wi];
                acc0 = fmaf(xl0[a], w, acc0);
            }
            float acc1 = 0.f;
#pragma unroll 1
            for (int a = 0; a < 4; a++) {
                int wi = 336 + a * 16 + b;
                float w = dotf4<16>(reinterpret_cast<const float4*>(W3 + wi * 64), h2) + B3[wi];
                acc1 = fmaf(ul1[a], w, acc1);
            }
            g_v[(size_t)b * E + e] = NORM * fmaf(sh0, acc0, I3 * acc1);
        }
#pragma unroll 1
        for (int j = 0; j < 4; j++) {
            float c01 = 0.f;
#pragma unroll 1
            for (int a = 0; a < 16; a++) {
                int wi = 256 + a * 4 + j;
                float w = dotf4<16>(reinterpret_cast<const float4*>(W3 + wi * 64), h2) + B3[wi];
                c01 = fmaf(xl0[a], w, c01);
            }
            float dx = 0.f, dy = 0.f, dz = 0.f;
#pragma unroll 1
            for (int a = 0; a < 4; a++) {
                int wi = 320 + a * 4 + j;
                float w = dotf4<16>(reinterpret_cast<const float4*>(W3 + wi * 64), h2) + B3[wi];
                dx = fmaf(xl1[a * 3 + 0], w, dx);
                dy = fmaf(xl1[a * 3 + 1], w, dy);
                dz = fmaf(xl1[a * 3 + 2], w, dz);
            }
            g_v[(size_t)(16 + j * 3 + 0) * E + e] = NORM * (shx * c01 + sh0 * dx);
            g_v[(size_t)(16 + j * 3 + 1) * E + e] = NORM * (shy * c01 + sh0 * dy);
            g_v[(size_t)(16 + j * 3 + 2) * E + e] = NORM * (shz * c01 + sh0 * dz);
        }
    }
}

// ---------------------------------------------------------------------------
__global__ void softmax_agg_kernel(const int* __restrict__ eidx, int E) {
    int e = blockIdx.x * blockDim.x + threadIdx.x;
    if (e >= E) return;
    int d = eidx[E + e];
    float p = __expf(g_logit[e] - g_m[d]);
    atomicAdd(&g_z[d], p);
#pragma unroll
    for (int j = 0; j < 28; j++)
        atomicAdd(&g_agg[(size_t)d * 28 + j], p * g_v[(size_t)j * E + e]);
}

// ---------------------------------------------------------------------------
__global__ void node_out_kernel(const float* __restrict__ na,
                                const float* __restrict__ Wo0,
                                const float* __restrict__ Wo1,
                                float* __restrict__ out, int N) {
    __shared__ float sW0[512], sW1[32];
    int tid = threadIdx.x;
    for (int i = tid; i < 512; i += blockDim.x) sW0[i] = Wo0[i];
    for (int i = tid; i < 32;  i += blockDim.x) sW1[i] = Wo1[i];
    __syncthreads();

    int n = blockIdx.x * blockDim.x + tid;
    if (n >= N) return;
    float z = g_z[n];
    float zi = z > 0.f ? 1.f / z : 0.f;
    float ag[28];
#pragma unroll
    for (int j = 0; j < 28; j++) ag[j] = g_agg[(size_t)n * 28 + j] * zi;

#pragma unroll
    for (int o = 0; o < 32; o++) {
        float s = 0.f;
#pragma unroll
        for (int a = 0; a < 16; a++) s = fmaf(ag[a], sW0[a * 32 + o], s);
        out[(size_t)n * 56 + o] = fmaf(s, 0.25f, na[(size_t)n * 56 + o]);
    }
#pragma unroll
    for (int o = 0; o < 8; o++)
#pragma unroll
        for (int c = 0; c < 3; c++) {
            float s = 0.f;
#pragma unroll
            for (int a = 0; a < 4; a++) s = fmaf(ag[16 + a * 3 + c], sW1[a * 8 + o], s);
            out[(size_t)n * 56 + 32 + o * 3 + c] =
                fmaf(s, 0.5f, na[(size_t)n * 56 + 32 + o * 3 + c]);
        }
}

// ---------------------------------------------------------------------------
extern "C" void kernel_launch(void* const* d_in, const int* in_sizes, int n_in,
                              void* d_out, int out_size) {
    const float* node_attr  = (const float*)d_in[0];
    const float* edge_attr  = (const float*)d_in[1];
    const float* edge_sh    = (const float*)d_in[2];
    const int*   edge_index = (const int*)  d_in[3];
    const float* W_in0  = (const float*)d_in[4];
    const float* W_in1  = (const float*)d_in[5];
    const float* Wq0    = (const float*)d_in[6];
    const float* Wq1    = (const float*)d_in[7];
    const float* Wd0    = (const float*)d_in[8];
    const float* Wd1    = (const float*)d_in[9];
    const float* W_out0 = (const float*)d_in[10];
    const float* W_out1 = (const float*)d_in[11];
    const float* fcW1 = (const float*)d_in[12];
    const float* fcb1 = (const float*)d_in[13];
    const float* fcW2 = (const float*)d_in[14];
    const float* fcb2 = (const float*)d_in[15];
    const float* fcW3 = (const float*)d_in[16];
    const float* fcb3 = (const float*)d_in[17];
    const float* fkW1 = (const float*)d_in[18];
    const float* fkb1 = (const float*)d_in[19];
    const float* fkW2 = (const float*)d_in[20];
    const float* fkb2 = (const float*)d_in[21];
    const float* fkW3 = (const float*)d_in[22];
    const float* fkb3 = (const float*)d_in[23];
    float* out = (float*)d_out;

    int N = in_sizes[0] / 56;
    int E = in_sizes[2] / 4;

    cudaFuncSetAttribute(edge_kernel,
                         cudaFuncAttributeMaxDynamicSharedMemorySize,
                         SM_FLOATS * (int)sizeof(float));

    node_prep_kernel<<<(N + 127) / 128, 128>>>(node_attr, W_in0, W_in1, Wq0, Wq1,
                                               Wd0, Wd1, N);
    init_kernel<<<(N * 28 + 255) / 256, 256>>>(N);
    edge_kernel<<<(E + 255) / 256, 256, SM_FLOATS * sizeof(float)>>>(
        edge_attr, edge_sh, edge_index,
        fcW1, fcb1, fcW2, fcb2, fcW3, fcb3,
        fkW1, fkb1, fkW2, fkb2, fkW3, fkb3, E);
    softmax_agg_kernel<<<(E + 255) / 256, 256>>>(edge_index, E);
    node_out_kernel<<<(N + 127) / 128, 128>>>(node_attr, W_out0, W_out1, out, N);
}

// round 4
// speedup vs baseline: 1.2819x; 1.2819x over previous
#include <cuda_runtime.h>
#include <cstdint>
#include <cstddef>

#define MAXN 10000
#define MAXE 160000
#define NSM  148

typedef unsigned long long ull;

__device__ float g_x0[MAXN * 16];
__device__ float g_x1[MAXN * 12];
__device__ float g_qd0[MAXN * 8];
__device__ float g_qd1[MAXN * 6];
__device__ float g_logit[MAXE];
__device__ float g_v[MAXE * 28];     // SoA: [j*E + e]
__device__ float g_m[MAXN];
__device__ float g_z[MAXN];
__device__ float g_agg[MAXN * 28];   // AoS

__device__ __forceinline__ float frelu(float x) { return x > 0.f ? x : 0.f; }

// ---- packed f32x2 helpers (Blackwell FFMA2) -------------------------------
__device__ __forceinline__ ull pack2(float lo, float hi) {
    ull r; asm("mov.b64 %0, {%1, %2};" : "=l"(r) : "f"(lo), "f"(hi)); return r;
}
__device__ __forceinline__ void unpack2(ull v, float& lo, float& hi) {
    asm("mov.b64 {%0, %1}, %2;" : "=f"(lo), "=f"(hi) : "l"(v));
}
__device__ __forceinline__ void ffma2(ull& d, ull a, ull b) {
    asm("fma.rn.f32x2 %0, %1, %2, %0;" : "+l"(d) : "l"(a), "l"(b));
}

// dot of (4*NU2) floats: w in smem (16B-aligned), h packed as b64 pairs
template <int NU2>
__device__ __forceinline__ float dotp(const float* __restrict__ w,
                                      const ull* __restrict__ h) {
    ull a0 = 0ull, a1 = 0ull;
    const ulonglong2* wp = reinterpret_cast<const ulonglong2*>(w);
#pragma unroll
    for (int t = 0; t < NU2; t++) {
        ulonglong2 ww = wp[t];          // 4 floats = 2 packed pairs
        ffma2(a0, ww.x, h[2 * t]);
        ffma2(a1, ww.y, h[2 * t + 1]);
    }
    float l0, h0, l1, h1;
    unpack2(a0, l0, h0);
    unpack2(a1, l1, h1);
    return (l0 + h0) + (l1 + h1);
}

__device__ __forceinline__ void atomicMaxF(float* addr, float v) {
    if (v >= 0.f) atomicMax((int*)addr, __float_as_int(v));
    else          atomicMin((unsigned int*)addr, __float_as_uint(v));
}

// ---------------------------------------------------------------------------
// Kernel A: node prep (x = ir_linear(node_attr); qd = (q @ Wd) precontracted)
// ---------------------------------------------------------------------------
__global__ void node_prep_kernel(const float* __restrict__ na,
                                 const float* __restrict__ Win0,
                                 const float* __restrict__ Win1,
                                 const float* __restrict__ Wq0,
                                 const float* __restrict__ Wq1,
                                 const float* __restrict__ Wd0,
                                 const float* __restrict__ Wd1,
                                 int N) {
    __shared__ float sWin0[512], sWin1[32], sWq0[128], sWq1[8], sWd0[64], sWd1[4];
    int tid = threadIdx.x;
    for (int i = tid; i < 512; i += blockDim.x) sWin0[i] = Win0[i];
    for (int i = tid; i < 32;  i += blockDim.x) sWin1[i] = Win1[i];
    for (int i = tid; i < 128; i += blockDim.x) sWq0[i]  = Wq0[i];
    for (int i = tid; i < 8;   i += blockDim.x) sWq1[i]  = Wq1[i];
    for (int i = tid; i < 64;  i += blockDim.x) sWd0[i]  = Wd0[i];
    for (int i = tid; i < 4;   i += blockDim.x) sWd1[i]  = Wd1[i];
    __syncthreads();

    int n = blockIdx.x * blockDim.x + tid;
    if (n >= N) return;

    const float* p = na + (size_t)n * 56;
    float a0[32], a1[24];
#pragma unroll
    for (int i = 0; i < 32; i++) a0[i] = p[i];
#pragma unroll
    for (int i = 0; i < 24; i++) a1[i] = p[32 + i];

    float x0[16];
#pragma unroll
    for (int o = 0; o < 16; o++) {
        float s = 0.f;
#pragma unroll
        for (int i = 0; i < 32; i++) s = fmaf(a0[i], sWin0[i * 16 + o], s);
        x0[o] = s * 0.17677669529663687f;   // 1/sqrt(32)
    }
    float x1[12];
#pragma unroll
    for (int o = 0; o < 4; o++)
#pragma unroll
        for (int c = 0; c < 3; c++) {
            float s = 0.f;
#pragma unroll
            for (int m = 0; m < 8; m++) s = fmaf(a1[m * 3 + c], sWin1[m * 4 + o], s);
            x1[o * 3 + c] = s * 0.35355339059327373f;  // 1/sqrt(8)
        }

    float q0[8];
#pragma unroll
    for (int b = 0; b < 8; b++) {
        float s = 0.f;
#pragma unroll
        for (int o = 0; o < 16; o++) s = fmaf(x0[o], sWq0[o * 8 + b], s);
        q0[b] = s * 0.25f;                   // 1/sqrt(16)
    }
    float q1[6];
#pragma unroll
    for (int j = 0; j < 2; j++)
#pragma unroll
        for (int c = 0; c < 3; c++) {
            float s = 0.f;
#pragma unroll
            for (int o = 0; o < 4; o++) s = fmaf(x1[o * 3 + c], sWq1[o * 2 + j], s);
            q1[j * 3 + c] = s * 0.5f;        // 1/sqrt(4)
        }

#pragma unroll
    for (int j = 0; j < 8; j++) {
        float s = 0.f;
#pragma unroll
        for (int i = 0; i < 8; i++) s = fmaf(q0[i], sWd0[i * 8 + j], s);
        g_qd0[(size_t)n * 8 + j] = s;
    }
#pragma unroll
    for (int j = 0; j < 2; j++)
#pragma unroll
        for (int c = 0; c < 3; c++) {
            float s = 0.f;
#pragma unroll
            for (int i = 0; i < 2; i++) s = fmaf(q1[i * 3 + c], sWd1[i * 2 + j], s);
            g_qd1[(size_t)n * 6 + j * 3 + c] = s;
        }

#pragma unroll
    for (int o = 0; o < 16; o++) g_x0[(size_t)n * 16 + o] = x0[o];
#pragma unroll
    for (int o = 0; o < 12; o++) g_x1[(size_t)n * 12 + o] = x1[o];
}

// ---------------------------------------------------------------------------
__global__ void init_kernel(int N) {
    int i = blockIdx.x * blockDim.x + threadIdx.x;
    if (i < N * 28) g_agg[i] = 0.f;
    if (i < N) {
        g_m[i] = __int_as_float(0xff800000);  // -inf
        g_z[i] = 0.f;
    }
}

// ---------------------------------------------------------------------------
// Kernel B: fused edge kernel (persistent CTAs, packed f32x2 math)
// smem layout (floats): K-MLP W1^T,b1,W2^T,b2,W3^T,b3 then V-MLP same.
// ---------------------------------------------------------------------------
#define OW1K 0
#define OB1K 2048
#define OW2K 2112
#define OB2K 6208
#define OW3K 6272
#define OB3K 19072
#define OW1V 19272
#define OB1V 21320
#define OW2V 21384
#define OB2V 25480
#define OW3V 25544
#define OB3V 51144
#define SM_FLOATS 51544

__device__ __forceinline__ void mlp_front_p(const float* __restrict__ sm,
                                            int oW1, int oB1, int oW2, int oB2,
                                            const float* __restrict__ gEa,
                                            ull* __restrict__ h2p) {
    ull eap[16];
#pragma unroll
    for (int t = 0; t < 8; t++) {
        float4 v = reinterpret_cast<const float4*>(gEa)[t];
        eap[2 * t]     = pack2(v.x, v.y);
        eap[2 * t + 1] = pack2(v.z, v.w);
    }
    ull h1p[32];
#pragma unroll
    for (int o = 0; o < 64; o += 2) {
        float lo = frelu(sm[oB1 + o]     + dotp<8>(sm + oW1 + o * 32,       eap));
        float hi = frelu(sm[oB1 + o + 1] + dotp<8>(sm + oW1 + (o + 1) * 32, eap));
        h1p[o >> 1] = pack2(lo, hi);
    }
#pragma unroll
    for (int o = 0; o < 64; o += 2) {
        float lo = frelu(sm[oB2 + o]     + dotp<16>(sm + oW2 + o * 64,       h1p));
        float hi = frelu(sm[oB2 + o + 1] + dotp<16>(sm + oW2 + (o + 1) * 64, h1p));
        h2p[o >> 1] = pack2(lo, hi);
    }
}

__global__ void __launch_bounds__(256, 1)
edge_kernel(const float* __restrict__ edge_attr,
            const float* __restrict__ edge_sh,
            const int*   __restrict__ eidx,
            const float* __restrict__ fcW1, const float* __restrict__ fcb1,
            const float* __restrict__ fcW2, const float* __restrict__ fcb2,
            const float* __restrict__ fcW3, const float* __restrict__ fcb3,
            const float* __restrict__ fkW1, const float* __restrict__ fkb1,
            const float* __restrict__ fkW2, const float* __restrict__ fkb2,
            const float* __restrict__ fkW3, const float* __restrict__ fkb3,
            int E) {
    extern __shared__ float sm[];
    int tid = threadIdx.x, bs = blockDim.x;
    for (int i = tid; i < 2048;  i += bs) { int o = i >> 5, c = i & 31; sm[OW1K + i] = fkW1[c * 64 + o]; }
    for (int i = tid; i < 64;    i += bs) sm[OB1K + i] = fkb1[i];
    for (int i = tid; i < 4096;  i += bs) { int o = i >> 6, c = i & 63; sm[OW2K + i] = fkW2[c * 64 + o]; }
    for (int i = tid; i < 64;    i += bs) sm[OB2K + i] = fkb2[i];
    for (int i = tid; i < 12800; i += bs) { int w = i >> 6, c = i & 63; sm[OW3K + i] = fkW3[c * 200 + w]; }
    for (int i = tid; i < 200;   i += bs) sm[OB3K + i] = fkb3[i];
    for (int i = tid; i < 2048;  i += bs) { int o = i >> 5, c = i & 31; sm[OW1V + i] = fcW1[c * 64 + o]; }
    for (int i = tid; i < 64;    i += bs) sm[OB1V + i] = fcb1[i];
    for (int i = tid; i < 4096;  i += bs) { int o = i >> 6, c = i & 63; sm[OW2V + i] = fcW2[c * 64 + o]; }
    for (int i = tid; i < 64;    i += bs) sm[OB2V + i] = fcb2[i];
    for (int i = tid; i < 25600; i += bs) { int w = i >> 6, c = i & 63; sm[OW3V + i] = fcW3[c * 400 + w]; }
    for (int i = tid; i < 400;   i += bs) sm[OB3V + i] = fcb3[i];
    __syncthreads();

    const float NORM = 0.22360679774997896f;  // 1/sqrt(20)
    const float I3   = 0.5773502691896258f;   // 1/sqrt(3)

    for (int e = blockIdx.x * bs + tid; e < E; e += gridDim.x * bs) {
        int s = eidx[e];
        int d = eidx[E + e];
        float4 shv = reinterpret_cast<const float4*>(edge_sh)[e];
        float sh0 = shv.x, shx = shv.y, shy = shv.z, shz = shv.w;

        float xl0[16], xl1[12], ul1[4];
#pragma unroll
        for (int o = 0; o < 16; o++) xl0[o] = g_x0[(size_t)s * 16 + o];
#pragma unroll
        for (int o = 0; o < 12; o++) xl1[o] = g_x1[(size_t)s * 12 + o];
#pragma unroll
        for (int j = 0; j < 4; j++)
            ul1[j] = xl1[j * 3] * shx + xl1[j * 3 + 1] * shy + xl1[j * 3 + 2] * shz;

        ull h2p[32];

        // ===================== K path =====================
        mlp_front_p(sm, OW1K, OB1K, OW2K, OB2K, edge_attr + (size_t)e * 32, h2p);
        {
            const float* W3 = sm + OW3K;
            const float* B3 = sm + OB3K;
            float logit = 0.f;
#pragma unroll 1
            for (int b = 0; b < 8; b++) {
                float acc0 = 0.f;
#pragma unroll 1
                for (int a = 0; a < 16; a++) {
                    int wi = a * 8 + b;
                    float w = dotp<16>(W3 + wi * 64, h2p) + B3[wi];
                    acc0 = fmaf(xl0[a], w, acc0);
                }
                float acc1 = 0.f;
#pragma unroll 1
                for (int a = 0; a < 4; a++) {
                    int wi = 168 + a * 8 + b;
                    float w = dotp<16>(W3 + wi * 64, h2p) + B3[wi];
                    acc1 = fmaf(ul1[a], w, acc1);
                }
                float k0b = NORM * fmaf(sh0, acc0, I3 * acc1);
                logit = fmaf(g_qd0[(size_t)d * 8 + b], k0b, logit);
            }
#pragma unroll 1
            for (int j = 0; j < 2; j++) {
                float c01 = 0.f;
#pragma unroll 1
                for (int a = 0; a < 16; a++) {
                    int wi = 128 + a * 2 + j;
                    float w = dotp<16>(W3 + wi * 64, h2p) + B3[wi];
                    c01 = fmaf(xl0[a], w, c01);
                }
                float dx = 0.f, dy = 0.f, dz = 0.f;
#pragma unroll 1
                for (int a = 0; a < 4; a++) {
                    int wi = 160 + a * 2 + j;
                    float w = dotp<16>(W3 + wi * 64, h2p) + B3[wi];
                    dx = fmaf(xl1[a * 3 + 0], w, dx);
                    dy = fmaf(xl1[a * 3 + 1], w, dy);
                    dz = fmaf(xl1[a * 3 + 2], w, dz);
                }
                float k1x = NORM * (shx * c01 + sh0 * dx);
                float k1y = NORM * (shy * c01 + sh0 * dy);
                float k1z = NORM * (shz * c01 + sh0 * dz);
                logit += I3 * (g_qd1[(size_t)d * 6 + j * 3 + 0] * k1x +
                               g_qd1[(size_t)d * 6 + j * 3 + 1] * k1y +
                               g_qd1[(size_t)d * 6 + j * 3 + 2] * k1z);
            }
            logit *= 0.31622776601683794f;  // 1/sqrt(10)
            g_logit[e] = logit;
            atomicMaxF(&g_m[d], logit);
        }

        // ===================== V path =====================
        mlp_front_p(sm, OW1V, OB1V, OW2V, OB2V, edge_attr + (size_t)e * 32, h2p);
        {
            const float* W3 = sm + OW3V;
            const float* B3 = sm + OB3V;
#pragma unroll 1
            for (int b = 0; b < 16; b++) {
                float acc0 = 0.f;
#pragma unroll 1
                for (int a = 0; a < 16; a++) {
                    int wi = a * 16 + b;
                    float w = dotp<16>(W3 + wi * 64, h2p) + B3[wi];
                    acc0 = fmaf(xl0[a], w, acc0);
                }
                float acc1 = 0.f;
#pragma unroll 1
                for (int a = 0; a < 4; a++) {
                    int wi = 336 + a * 16 + b;
                    float w = dotp<16>(W3 + wi * 64, h2p) + B3[wi];
                    acc1 = fmaf(ul1[a], w, acc1);
                }
                g_v[(size_t)b * E + e] = NORM * fmaf(sh0, acc0, I3 * acc1);
            }
#pragma unroll 1
            for (int j = 0; j < 4; j++) {
                float c01 = 0.f;
#pragma unroll 1
                for (int a = 0; a < 16; a++) {
                    int wi = 256 + a * 4 + j;
                    float w = dotp<16>(W3 + wi * 64, h2p) + B3[wi];
                    c01 = fmaf(xl0[a], w, c01);
                }
                float dx = 0.f, dy = 0.f, dz = 0.f;
#pragma unroll 1
                for (int a = 0; a < 4; a++) {
                    int wi = 320 + a * 4 + j;
                    float w = dotp<16>(W3 + wi * 64, h2p) + B3[wi];
                    dx = fmaf(xl1[a * 3 + 0], w, dx);
                    dy = fmaf(xl1[a * 3 + 1], w, dy);
                    dz = fmaf(xl1[a * 3 + 2], w, dz);
                }
                g_v[(size_t)(16 + j * 3 + 0) * E + e] = NORM * (shx * c01 + sh0 * dx);
                g_v[(size_t)(16 + j * 3 + 1) * E + e] = NORM * (shy * c01 + sh0 * dy);
                g_v[(size_t)(16 + j * 3 + 2) * E + e] = NORM * (shz * c01 + sh0 * dz);
            }
        }
    }
}

// ---------------------------------------------------------------------------
__global__ void softmax_agg_kernel(const int* __restrict__ eidx, int E) {
    int e = blockIdx.x * blockDim.x + threadIdx.x;
    if (e >= E) return;
    int d = eidx[E + e];
    float p = __expf(g_logit[e] - g_m[d]);
    atomicAdd(&g_z[d], p);
#pragma unroll
    for (int j = 0; j < 28; j++)
        atomicAdd(&g_agg[(size_t)d * 28 + j], p * g_v[(size_t)j * E + e]);
}

// ---------------------------------------------------------------------------
__global__ void node_out_kernel(const float* __restrict__ na,
                                const float* __restrict__ Wo0,
                                const float* __restrict__ Wo1,
                                float* __restrict__ out, int N) {
    __shared__ float sW0[512], sW1[32];
    int tid = threadIdx.x;
    for (int i = tid; i < 512; i += blockDim.x) sW0[i] = Wo0[i];
    for (int i = tid; i < 32;  i += blockDim.x) sW1[i] = Wo1[i];
    __syncthreads();

    int n = blockIdx.x * blockDim.x + tid;
    if (n >= N) return;
    float z = g_z[n];
    float zi = z > 0.f ? 1.f / z : 0.f;
    float ag[28];
#pragma unroll
    for (int j = 0; j < 28; j++) ag[j] = g_agg[(size_t)n * 28 + j] * zi;

#pragma unroll
    for (int o = 0; o < 32; o++) {
        float s = 0.f;
#pragma unroll
        for (int a = 0; a < 16; a++) s = fmaf(ag[a], sW0[a * 32 + o], s);
        out[(size_t)n * 56 + o] = fmaf(s, 0.25f, na[(size_t)n * 56 + o]);
    }
#pragma unroll
    for (int o = 0; o < 8; o++)
#pragma unroll
        for (int c = 0; c < 3; c++) {
            float s = 0.f;
#pragma unroll
            for (int a = 0; a < 4; a++) s = fmaf(ag[16 + a * 3 + c], sW1[a * 8 + o], s);
            out[(size_t)n * 56 + 32 + o * 3 + c] =
                fmaf(s, 0.5f, na[(size_t)n * 56 + 32 + o * 3 + c]);
        }
}

// ---------------------------------------------------------------------------
extern "C" void kernel_launch(void* const* d_in, const int* in_sizes, int n_in,
                              void* d_out, int out_size) {
    const float* node_attr  = (const float*)d_in[0];
    const float* edge_attr  = (const float*)d_in[1];
    const float* edge_sh    = (const float*)d_in[2];
    const int*   edge_index = (const int*)  d_in[3];
    const float* W_in0  = (const float*)d_in[4];
    const float* W_in1  = (const float*)d_in[5];
    const float* Wq0    = (const float*)d_in[6];
    const float* Wq1    = (const float*)d_in[7];
    const float* Wd0    = (const float*)d_in[8];
    const float* Wd1    = (const float*)d_in[9];
    const float* W_out0 = (const float*)d_in[10];
    const float* W_out1 = (const float*)d_in[11];
    const float* fcW1 = (const float*)d_in[12];
    const float* fcb1 = (const float*)d_in[13];
    const float* fcW2 = (const float*)d_in[14];
    const float* fcb2 = (const float*)d_in[15];
    const float* fcW3 = (const float*)d_in[16];
    const float* fcb3 = (const float*)d_in[17];
    const float* fkW1 = (const float*)d_in[18];
    const float* fkb1 = (const float*)d_in[19];
    const float* fkW2 = (const float*)d_in[20];
    const float* fkb2 = (const float*)d_in[21];
    const float* fkW3 = (const float*)d_in[22];
    const float* fkb3 = (const float*)d_in[23];
    float* out = (float*)d_out;

    int N = in_sizes[0] / 56;
    int E = in_sizes[2] / 4;

    cudaFuncSetAttribute(edge_kernel,
                         cudaFuncAttributeMaxDynamicSharedMemorySize,
                         SM_FLOATS * (int)sizeof(float));

    node_prep_kernel<<<(N + 127) / 128, 128>>>(node_attr, W_in0, W_in1, Wq0, Wq1,
                                               Wd0, Wd1, N);
    init_kernel<<<(N * 28 + 255) / 256, 256>>>(N);
    edge_kernel<<<NSM, 256, SM_FLOATS * sizeof(float)>>>(
        edge_attr, edge_sh, edge_index,
        fcW1, fcb1, fcW2, fcb2, fcW3, fcb3,
        fkW1, fkb1, fkW2, fkb2, fkW3, fkb3, E);
    softmax_agg_kernel<<<(E + 255) / 256, 256>>>(edge_index, E);
    node_out_kernel<<<(N + 127) / 128, 128>>>(node_attr, W_out0, W_out1, out, N);
}